// round 3
// baseline (speedup 1.0000x reference)
#include <cuda_runtime.h>
#include <cstdint>
#include <cstddef>

#define NN 16384          // nodes / edges
#define AA 16384          // bond_n rows
#define DD 128            // emb dim
#define K2 256            // 2*D
#define RS 132            // smem row stride (pad vs 128 to avoid conflicts)
#define KP 32             // k per phase

// ---------------- device scratch (no allocation allowed) ----------------
__device__ float g_colw[NN];
__device__ float g_m[DD];
__device__ float g_hn[(size_t)NN * DD];
__device__ float g_WiT[K2 * DD];   // [k][d] = Wi2[d][k]
__device__ float g_WmT[DD * DD];   // [k][d] = Wm2[d][k]

// ---------------- f32x2 helpers (Blackwell packed fp32 FMA) ----------------
__device__ __forceinline__ unsigned long long f2pack(float lo, float hi) {
    unsigned long long r;
    asm("mov.b64 %0, {%1, %2};" : "=l"(r) : "f"(lo), "f"(hi));
    return r;
}
__device__ __forceinline__ unsigned long long ffma2(unsigned long long a,
                                                    unsigned long long b,
                                                    unsigned long long c) {
    unsigned long long d;
    asm("fma.rn.f32x2 %0, %1, %2, %3;" : "=l"(d) : "l"(a), "l"(b), "l"(c));
    return d;
}
__device__ __forceinline__ float2 f2unpack(unsigned long long v) {
    float2 f;
    asm("mov.b64 {%0, %1}, %2;" : "=f"(f.x), "=f"(f.y) : "l"(v));
    return f;
}

// ---------------- kernel 1: zero scratch + transpose weights ----------------
__global__ void __launch_bounds__(256) prep_kernel(const float* __restrict__ Wi2,
                                                   const float* __restrict__ Wm2) {
    int g = blockIdx.x * 256 + threadIdx.x;   // 128 blocks * 256 = 32768
    {   // WiT[k*128+d] = Wi2[d*256+k]    (32768 elems)
        int k = g >> 7, d = g & 127;
        g_WiT[g] = Wi2[d * K2 + k];
    }
    if (g < DD * DD) {                        // WmT[k*128+d] = Wm2[d*128+k]
        int k = g >> 7, d = g & 127;
        g_WmT[g] = Wm2[d * DD + k];
    }
    if (g < NN) g_colw[g] = 0.0f;
    if (g < DD) g_m[g] = 0.0f;
}

// ---------------- kernel 2: col_w = sum over rows of bond_n (1 GB stream) ----------------
__global__ void __launch_bounds__(256) colw_kernel(const float* __restrict__ bond) {
    const int c4 = blockIdx.x * 256 + threadIdx.x;   // float4 column index, [0,4096)
    const int a0 = blockIdx.y * 256;                 // 64 row-slices of 256 rows
    const float4* p = reinterpret_cast<const float4*>(bond) + (size_t)a0 * 4096 + c4;

    float4 s0 = make_float4(0.f, 0.f, 0.f, 0.f);
    float4 s1 = s0, s2 = s0, s3 = s0;
    for (int i = 0; i < 64; ++i) {
        float4 v0 = __ldcs(p);
        float4 v1 = __ldcs(p + 4096);
        float4 v2 = __ldcs(p + 8192);
        float4 v3 = __ldcs(p + 12288);
        p += 16384;
        s0.x += v0.x; s0.y += v0.y; s0.z += v0.z; s0.w += v0.w;
        s1.x += v1.x; s1.y += v1.y; s1.z += v1.z; s1.w += v1.w;
        s2.x += v2.x; s2.y += v2.y; s2.z += v2.z; s2.w += v2.w;
        s3.x += v3.x; s3.y += v3.y; s3.z += v3.z; s3.w += v3.w;
    }
    float sx = (s0.x + s1.x) + (s2.x + s3.x);
    float sy = (s0.y + s1.y) + (s2.y + s3.y);
    float sz = (s0.z + s1.z) + (s2.z + s3.z);
    float sw = (s0.w + s1.w) + (s2.w + s3.w);
    float* dst = &g_colw[c4 * 4];
    atomicAdd(dst + 0, sx);
    atomicAdd(dst + 1, sy);
    atomicAdd(dst + 2, sz);
    atomicAdd(dst + 3, sw);
}

// ---------------- kernel 3: embeddings + h_n GEMM + m partial reduction ----------------
// Block: 128 rows x 128 cols output. 256 threads: tx = tid&31 (4 cols each as float4),
// ty = tid>>5 (16 rows each). Accumulators: 8 row-pairs x 4 cols of f32x2.
__global__ void __launch_bounds__(256) gemm_kernel(const int* __restrict__ x,
                                                   const int* __restrict__ ea,
                                                   const float* __restrict__ atom_emb,
                                                   const float* __restrict__ bond_emb,
                                                   const float* __restrict__ Wib2) {
    __shared__ __align__(16) float sm[2 * KP * RS];   // catT | wiT, 33 KB
    float* catT = sm;             // [KP][RS] : catT[k][r] = cat[row0+r][k0+k]
    float* wiT  = sm + KP * RS;   // [KP][RS] : wiT[k][d]  = Wi2[d][k0+k]

    const int tid = threadIdx.x;
    const int tx = tid & 31;      // col group (4 cols)
    const int ty = tid >> 5;      // row group (16 rows)
    const int row0 = blockIdx.x * 128;

    unsigned long long acc[8][4];
    {
        float4 bias = *reinterpret_cast<const float4*>(&Wib2[tx * 4]);
        unsigned long long b0 = f2pack(bias.x, bias.x);
        unsigned long long b1 = f2pack(bias.y, bias.y);
        unsigned long long b2 = f2pack(bias.z, bias.z);
        unsigned long long b3 = f2pack(bias.w, bias.w);
        #pragma unroll
        for (int rp = 0; rp < 8; ++rp) {
            acc[rp][0] = b0; acc[rp][1] = b1; acc[rp][2] = b2; acc[rp][3] = b3;
        }
    }

    #pragma unroll 1
    for (int p = 0; p < 8; ++p) {
        __syncthreads();
        const float* src = (p < 4) ? atom_emb : bond_emb;
        const int2* idx  = (p < 4) ? reinterpret_cast<const int2*>(x)
                                   : reinterpret_cast<const int2*>(ea);
        const int kqbase = (p & 3) * 8;   // float4-column base within the 128-wide half

        // fill catT: 8 kq x 128 r items; lanes cover consecutive r -> conflict-free STS
        #pragma unroll
        for (int it = 0; it < 4; ++it) {
            int gid = it * 256 + tid;     // [0,1024)
            int kq = gid >> 7;            // [0,8)
            int r  = gid & 127;
            int2 ii = idx[row0 + r];
            float4 e0 = reinterpret_cast<const float4*>(src)[ii.x * 32 + kqbase + kq];
            float4 e1 = reinterpret_cast<const float4*>(src)[ii.y * 32 + kqbase + kq];
            int kb = kq * 4;
            catT[(kb + 0) * RS + r] = e0.x + e1.x;
            catT[(kb + 1) * RS + r] = e0.y + e1.y;
            catT[(kb + 2) * RS + r] = e0.z + e1.z;
            catT[(kb + 3) * RS + r] = e0.w + e1.w;
        }
        // fill wiT from pre-transposed g_WiT (coalesced loads, conflict-free stores)
        const int k0 = p * KP;
        #pragma unroll
        for (int it = 0; it < 4; ++it) {
            int gid = it * 256 + tid;     // [0,1024)
            int k  = gid >> 5;            // [0,32)
            int d4 = gid & 31;
            float4 v = reinterpret_cast<const float4*>(g_WiT)[(k0 + k) * 32 + d4];
            *reinterpret_cast<float4*>(&wiT[k * RS + d4 * 4]) = v;
        }
        __syncthreads();

        // compute: a-loads are full-warp broadcasts, b-loads consecutive float4
        #pragma unroll 2
        for (int k = 0; k < KP; ++k) {
            const float* ar = &catT[k * RS + ty * 16];
            ulonglong2 a01 = *reinterpret_cast<const ulonglong2*>(ar);
            ulonglong2 a23 = *reinterpret_cast<const ulonglong2*>(ar + 4);
            ulonglong2 a45 = *reinterpret_cast<const ulonglong2*>(ar + 8);
            ulonglong2 a67 = *reinterpret_cast<const ulonglong2*>(ar + 12);
            float4 b = *reinterpret_cast<const float4*>(&wiT[k * RS + tx * 4]);
            unsigned long long bb0 = f2pack(b.x, b.x);
            unsigned long long bb1 = f2pack(b.y, b.y);
            unsigned long long bb2 = f2pack(b.z, b.z);
            unsigned long long bb3 = f2pack(b.w, b.w);
            acc[0][0] = ffma2(a01.x, bb0, acc[0][0]);
            acc[0][1] = ffma2(a01.x, bb1, acc[0][1]);
            acc[0][2] = ffma2(a01.x, bb2, acc[0][2]);
            acc[0][3] = ffma2(a01.x, bb3, acc[0][3]);
            acc[1][0] = ffma2(a01.y, bb0, acc[1][0]);
            acc[1][1] = ffma2(a01.y, bb1, acc[1][1]);
            acc[1][2] = ffma2(a01.y, bb2, acc[1][2]);
            acc[1][3] = ffma2(a01.y, bb3, acc[1][3]);
            acc[2][0] = ffma2(a23.x, bb0, acc[2][0]);
            acc[2][1] = ffma2(a23.x, bb1, acc[2][1]);
            acc[2][2] = ffma2(a23.x, bb2, acc[2][2]);
            acc[2][3] = ffma2(a23.x, bb3, acc[2][3]);
            acc[3][0] = ffma2(a23.y, bb0, acc[3][0]);
            acc[3][1] = ffma2(a23.y, bb1, acc[3][1]);
            acc[3][2] = ffma2(a23.y, bb2, acc[3][2]);
            acc[3][3] = ffma2(a23.y, bb3, acc[3][3]);
            acc[4][0] = ffma2(a45.x, bb0, acc[4][0]);
            acc[4][1] = ffma2(a45.x, bb1, acc[4][1]);
            acc[4][2] = ffma2(a45.x, bb2, acc[4][2]);
            acc[4][3] = ffma2(a45.x, bb3, acc[4][3]);
            acc[5][0] = ffma2(a45.y, bb0, acc[5][0]);
            acc[5][1] = ffma2(a45.y, bb1, acc[5][1]);
            acc[5][2] = ffma2(a45.y, bb2, acc[5][2]);
            acc[5][3] = ffma2(a45.y, bb3, acc[5][3]);
            acc[6][0] = ffma2(a67.x, bb0, acc[6][0]);
            acc[6][1] = ffma2(a67.x, bb1, acc[6][1]);
            acc[6][2] = ffma2(a67.x, bb2, acc[6][2]);
            acc[6][3] = ffma2(a67.x, bb3, acc[6][3]);
            acc[7][0] = ffma2(a67.y, bb0, acc[7][0]);
            acc[7][1] = ffma2(a67.y, bb1, acc[7][1]);
            acc[7][2] = ffma2(a67.y, bb2, acc[7][2]);
            acc[7][3] = ffma2(a67.y, bb3, acc[7][3]);
        }
    }

    // epilogue: relu, store h_n, accumulate m partials
    float cw[16];
    #pragma unroll
    for (int i = 0; i < 16; ++i) cw[i] = g_colw[row0 + ty * 16 + i];

    float md0 = 0.f, md1 = 0.f, md2 = 0.f, md3 = 0.f;
    #pragma unroll
    for (int rp = 0; rp < 8; ++rp) {
        float2 v0 = f2unpack(acc[rp][0]);
        float2 v1 = f2unpack(acc[rp][1]);
        float2 v2 = f2unpack(acc[rp][2]);
        float2 v3 = f2unpack(acc[rp][3]);
        v0.x = fmaxf(v0.x, 0.f); v0.y = fmaxf(v0.y, 0.f);
        v1.x = fmaxf(v1.x, 0.f); v1.y = fmaxf(v1.y, 0.f);
        v2.x = fmaxf(v2.x, 0.f); v2.y = fmaxf(v2.y, 0.f);
        v3.x = fmaxf(v3.x, 0.f); v3.y = fmaxf(v3.y, 0.f);
        int r = row0 + ty * 16 + rp * 2;
        *reinterpret_cast<float4*>(&g_hn[(size_t)r * DD + tx * 4]) =
            make_float4(v0.x, v1.x, v2.x, v3.x);
        *reinterpret_cast<float4*>(&g_hn[(size_t)(r + 1) * DD + tx * 4]) =
            make_float4(v0.y, v1.y, v2.y, v3.y);
        float c0 = cw[rp * 2], c1 = cw[rp * 2 + 1];
        md0 += c0 * v0.x + c1 * v0.y;
        md1 += c0 * v1.x + c1 * v1.y;
        md2 += c0 * v2.x + c1 * v2.y;
        md3 += c0 * v3.x + c1 * v3.y;
    }

    __syncthreads();                 // smem no longer read by compute
    float* red = sm;                 // reuse as [8][128]
    red[ty * 128 + tx * 4 + 0] = md0;
    red[ty * 128 + tx * 4 + 1] = md1;
    red[ty * 128 + tx * 4 + 2] = md2;
    red[ty * 128 + tx * 4 + 3] = md3;
    __syncthreads();
    if (tid < 128) {
        float s = 0.f;
        #pragma unroll
        for (int t = 0; t < 8; ++t) s += red[t * 128 + tid];
        atomicAdd(&g_m[tid], s);
    }
}

// ---------------- kernel 4: mm = Wm2 @ m + b ; out = relu(h_n + mm) ----------------
__global__ void __launch_bounds__(256) epi_kernel(const float* __restrict__ Wmb2,
                                                  float* __restrict__ out) {
    __shared__ __align__(16) float mm[DD];
    const int tid = threadIdx.x;
    if (tid < DD) {
        float s = Wmb2[tid];
        #pragma unroll 8
        for (int k = 0; k < DD; ++k) s += g_m[k] * g_WmT[k * DD + tid];
        mm[tid] = s;
    }
    __syncthreads();
    const int tx = tid & 31, ro = tid >> 5;
    float4 mv = *reinterpret_cast<const float4*>(&mm[tx * 4]);
    const int row0 = blockIdx.x * 128;
    #pragma unroll 4
    for (int i = 0; i < 16; ++i) {
        int r = row0 + i * 8 + ro;
        float4 h = *reinterpret_cast<const float4*>(&g_hn[(size_t)r * DD + tx * 4]);
        float4 o;
        o.x = fmaxf(h.x + mv.x, 0.f);
        o.y = fmaxf(h.y + mv.y, 0.f);
        o.z = fmaxf(h.z + mv.z, 0.f);
        o.w = fmaxf(h.w + mv.w, 0.f);
        *reinterpret_cast<float4*>(&out[(size_t)r * DD + tx * 4]) = o;
    }
}

// ---------------- launch ----------------
extern "C" void kernel_launch(void* const* d_in, const int* in_sizes, int n_in,
                              void* d_out, int out_size) {
    const int*   x    = (const int*)d_in[0];
    const int*   ea   = (const int*)d_in[1];
    const float* bond = (const float*)d_in[2];
    const float* aemb = (const float*)d_in[3];
    const float* bemb = (const float*)d_in[4];
    const float* Wi_w = (const float*)d_in[5];
    const float* Wi_b = (const float*)d_in[6];
    const float* Wm_w = (const float*)d_in[7];
    const float* Wm_b = (const float*)d_in[8];
    float* out = (float*)d_out;

    // only layer L-1 = 2 contributes to the output (h is not fed back)
    const float* Wi2  = Wi_w + 2 * DD * K2;
    const float* Wib2 = Wi_b + 2 * DD;
    const float* Wm2  = Wm_w + 2 * DD * DD;
    const float* Wmb2 = Wm_b + 2 * DD;

    prep_kernel<<<128, 256>>>(Wi2, Wm2);
    colw_kernel<<<dim3(16, 64), 256>>>(bond);
    gemm_kernel<<<128, 256>>>(x, ea, aemb, bemb, Wib2);
    epi_kernel<<<128, 256>>>(Wmb2, out);
}

// round 4
// speedup vs baseline: 1.0175x; 1.0175x over previous
#include <cuda_runtime.h>
#include <cstdint>
#include <cstddef>

#define NN 16384          // nodes / edges
#define DD 128            // emb dim
#define K2 256            // 2*D
#define RS 132            // smem row stride (pad vs 128 to avoid conflicts)
#define KP 32             // k per phase
#define MB 256            // m-reduction blocks

// ---------------- device scratch (no allocation allowed) ----------------
__device__ float g_colw[NN];
__device__ float g_mp[MB * DD];    // per-block partials of m
__device__ float g_mm[DD];         // relu-input shift: Wm2 @ m + b
__device__ float g_hn[(size_t)NN * DD];
__device__ float g_WiT[K2 * DD];   // [k][d] = Wi2[d][k]
__device__ float g_WmT[DD * DD];   // [k][d] = Wm2[d][k]

// ---------------- f32x2 helpers (Blackwell packed fp32 FMA) ----------------
__device__ __forceinline__ unsigned long long f2pack(float lo, float hi) {
    unsigned long long r;
    asm("mov.b64 %0, {%1, %2};" : "=l"(r) : "f"(lo), "f"(hi));
    return r;
}
__device__ __forceinline__ unsigned long long ffma2(unsigned long long a,
                                                    unsigned long long b,
                                                    unsigned long long c) {
    unsigned long long d;
    asm("fma.rn.f32x2 %0, %1, %2, %3;" : "=l"(d) : "l"(a), "l"(b), "l"(c));
    return d;
}
__device__ __forceinline__ float2 f2unpack(unsigned long long v) {
    float2 f;
    asm("mov.b64 {%0, %1}, %2;" : "=f"(f.x), "=f"(f.y) : "l"(v));
    return f;
}

// ---------------- zero col_w accumulator (main stream, before colw) ----------------
__global__ void __launch_bounds__(256) zcolw_kernel() {
    int g = blockIdx.x * 256 + threadIdx.x;   // 64 * 256 = 16384
    g_colw[g] = 0.0f;
}

// ---------------- side stream: transpose weights ----------------
__global__ void __launch_bounds__(256) prep_kernel(const float* __restrict__ Wi2,
                                                   const float* __restrict__ Wm2) {
    int g = blockIdx.x * 256 + threadIdx.x;   // 128 blocks * 256 = 32768
    {   // WiT[k*128+d] = Wi2[d*256+k]
        int k = g >> 7, d = g & 127;
        g_WiT[g] = Wi2[d * K2 + k];
    }
    if (g < DD * DD) {                        // WmT[k*128+d] = Wm2[d*128+k]
        int k = g >> 7, d = g & 127;
        g_WmT[g] = Wm2[d * DD + k];
    }
}

// ---------------- main stream: col_w = bond_n.sum(axis=0) (1 GB stream) ----------------
__global__ void __launch_bounds__(256) colw_kernel(const float* __restrict__ bond) {
    const int c4 = blockIdx.x * 256 + threadIdx.x;   // float4 column index, [0,4096)
    const int a0 = blockIdx.y * 256;                 // 64 row-slices of 256 rows
    const float4* p = reinterpret_cast<const float4*>(bond) + (size_t)a0 * 4096 + c4;

    float4 s0 = make_float4(0.f, 0.f, 0.f, 0.f);
    float4 s1 = s0, s2 = s0, s3 = s0;
    for (int i = 0; i < 64; ++i) {
        float4 v0 = __ldcs(p);
        float4 v1 = __ldcs(p + 4096);
        float4 v2 = __ldcs(p + 8192);
        float4 v3 = __ldcs(p + 12288);
        p += 16384;
        s0.x += v0.x; s0.y += v0.y; s0.z += v0.z; s0.w += v0.w;
        s1.x += v1.x; s1.y += v1.y; s1.z += v1.z; s1.w += v1.w;
        s2.x += v2.x; s2.y += v2.y; s2.z += v2.z; s2.w += v2.w;
        s3.x += v3.x; s3.y += v3.y; s3.z += v3.z; s3.w += v3.w;
    }
    float sx = (s0.x + s1.x) + (s2.x + s3.x);
    float sy = (s0.y + s1.y) + (s2.y + s3.y);
    float sz = (s0.z + s1.z) + (s2.z + s3.z);
    float sw = (s0.w + s1.w) + (s2.w + s3.w);
    float* dst = &g_colw[c4 * 4];
    atomicAdd(dst + 0, sx);
    atomicAdd(dst + 1, sy);
    atomicAdd(dst + 2, sz);
    atomicAdd(dst + 3, sw);
}

// ---------------- side stream: embeddings + h_n GEMM (no colw dependency) ----------------
// Block: 128 rows x 128 cols output. 256 threads: tx = tid&31 (4 cols as float4),
// ty = tid>>5 (16 rows). Accumulators: 8 row-pairs x 4 cols of f32x2.
__global__ void __launch_bounds__(256) gemm_kernel(const int* __restrict__ x,
                                                   const int* __restrict__ ea,
                                                   const float* __restrict__ atom_emb,
                                                   const float* __restrict__ bond_emb,
                                                   const float* __restrict__ Wib2) {
    __shared__ __align__(16) float sm[2 * KP * RS];   // catT | wiT, 33 KB
    float* catT = sm;             // [KP][RS] : catT[k][r] = cat[row0+r][k0+k]
    float* wiT  = sm + KP * RS;   // [KP][RS] : wiT[k][d]  = Wi2[d][k0+k]

    const int tid = threadIdx.x;
    const int tx = tid & 31;
    const int ty = tid >> 5;
    const int row0 = blockIdx.x * 128;

    unsigned long long acc[8][4];
    {
        float4 bias = *reinterpret_cast<const float4*>(&Wib2[tx * 4]);
        unsigned long long b0 = f2pack(bias.x, bias.x);
        unsigned long long b1 = f2pack(bias.y, bias.y);
        unsigned long long b2 = f2pack(bias.z, bias.z);
        unsigned long long b3 = f2pack(bias.w, bias.w);
        #pragma unroll
        for (int rp = 0; rp < 8; ++rp) {
            acc[rp][0] = b0; acc[rp][1] = b1; acc[rp][2] = b2; acc[rp][3] = b3;
        }
    }

    #pragma unroll 1
    for (int p = 0; p < 8; ++p) {
        __syncthreads();
        const float* src = (p < 4) ? atom_emb : bond_emb;
        const int2* idx  = (p < 4) ? reinterpret_cast<const int2*>(x)
                                   : reinterpret_cast<const int2*>(ea);
        const int kqbase = (p & 3) * 8;

        // fill catT: lanes cover consecutive r -> conflict-free STS
        #pragma unroll
        for (int it = 0; it < 4; ++it) {
            int gid = it * 256 + tid;
            int kq = gid >> 7;
            int r  = gid & 127;
            int2 ii = idx[row0 + r];
            float4 e0 = reinterpret_cast<const float4*>(src)[ii.x * 32 + kqbase + kq];
            float4 e1 = reinterpret_cast<const float4*>(src)[ii.y * 32 + kqbase + kq];
            int kb = kq * 4;
            catT[(kb + 0) * RS + r] = e0.x + e1.x;
            catT[(kb + 1) * RS + r] = e0.y + e1.y;
            catT[(kb + 2) * RS + r] = e0.z + e1.z;
            catT[(kb + 3) * RS + r] = e0.w + e1.w;
        }
        // fill wiT from pre-transposed g_WiT
        const int k0 = p * KP;
        #pragma unroll
        for (int it = 0; it < 4; ++it) {
            int gid = it * 256 + tid;
            int k  = gid >> 5;
            int d4 = gid & 31;
            float4 v = reinterpret_cast<const float4*>(g_WiT)[(k0 + k) * 32 + d4];
            *reinterpret_cast<float4*>(&wiT[k * RS + d4 * 4]) = v;
        }
        __syncthreads();

        #pragma unroll 2
        for (int k = 0; k < KP; ++k) {
            const float* ar = &catT[k * RS + ty * 16];
            ulonglong2 a01 = *reinterpret_cast<const ulonglong2*>(ar);
            ulonglong2 a23 = *reinterpret_cast<const ulonglong2*>(ar + 4);
            ulonglong2 a45 = *reinterpret_cast<const ulonglong2*>(ar + 8);
            ulonglong2 a67 = *reinterpret_cast<const ulonglong2*>(ar + 12);
            float4 b = *reinterpret_cast<const float4*>(&wiT[k * RS + tx * 4]);
            unsigned long long bb0 = f2pack(b.x, b.x);
            unsigned long long bb1 = f2pack(b.y, b.y);
            unsigned long long bb2 = f2pack(b.z, b.z);
            unsigned long long bb3 = f2pack(b.w, b.w);
            acc[0][0] = ffma2(a01.x, bb0, acc[0][0]);
            acc[0][1] = ffma2(a01.x, bb1, acc[0][1]);
            acc[0][2] = ffma2(a01.x, bb2, acc[0][2]);
            acc[0][3] = ffma2(a01.x, bb3, acc[0][3]);
            acc[1][0] = ffma2(a01.y, bb0, acc[1][0]);
            acc[1][1] = ffma2(a01.y, bb1, acc[1][1]);
            acc[1][2] = ffma2(a01.y, bb2, acc[1][2]);
            acc[1][3] = ffma2(a01.y, bb3, acc[1][3]);
            acc[2][0] = ffma2(a23.x, bb0, acc[2][0]);
            acc[2][1] = ffma2(a23.x, bb1, acc[2][1]);
            acc[2][2] = ffma2(a23.x, bb2, acc[2][2]);
            acc[2][3] = ffma2(a23.x, bb3, acc[2][3]);
            acc[3][0] = ffma2(a23.y, bb0, acc[3][0]);
            acc[3][1] = ffma2(a23.y, bb1, acc[3][1]);
            acc[3][2] = ffma2(a23.y, bb2, acc[3][2]);
            acc[3][3] = ffma2(a23.y, bb3, acc[3][3]);
            acc[4][0] = ffma2(a45.x, bb0, acc[4][0]);
            acc[4][1] = ffma2(a45.x, bb1, acc[4][1]);
            acc[4][2] = ffma2(a45.x, bb2, acc[4][2]);
            acc[4][3] = ffma2(a45.x, bb3, acc[4][3]);
            acc[5][0] = ffma2(a45.y, bb0, acc[5][0]);
            acc[5][1] = ffma2(a45.y, bb1, acc[5][1]);
            acc[5][2] = ffma2(a45.y, bb2, acc[5][2]);
            acc[5][3] = ffma2(a45.y, bb3, acc[5][3]);
            acc[6][0] = ffma2(a67.x, bb0, acc[6][0]);
            acc[6][1] = ffma2(a67.x, bb1, acc[6][1]);
            acc[6][2] = ffma2(a67.x, bb2, acc[6][2]);
            acc[6][3] = ffma2(a67.x, bb3, acc[6][3]);
            acc[7][0] = ffma2(a67.y, bb0, acc[7][0]);
            acc[7][1] = ffma2(a67.y, bb1, acc[7][1]);
            acc[7][2] = ffma2(a67.y, bb2, acc[7][2]);
            acc[7][3] = ffma2(a67.y, bb3, acc[7][3]);
        }
    }

    // epilogue: relu + store h_n only (m reduction moved to m_kernel)
    #pragma unroll
    for (int rp = 0; rp < 8; ++rp) {
        float2 v0 = f2unpack(acc[rp][0]);
        float2 v1 = f2unpack(acc[rp][1]);
        float2 v2 = f2unpack(acc[rp][2]);
        float2 v3 = f2unpack(acc[rp][3]);
        int r = row0 + ty * 16 + rp * 2;
        *reinterpret_cast<float4*>(&g_hn[(size_t)r * DD + tx * 4]) =
            make_float4(fmaxf(v0.x, 0.f), fmaxf(v1.x, 0.f),
                        fmaxf(v2.x, 0.f), fmaxf(v3.x, 0.f));
        *reinterpret_cast<float4*>(&g_hn[(size_t)(r + 1) * DD + tx * 4]) =
            make_float4(fmaxf(v0.y, 0.f), fmaxf(v1.y, 0.f),
                        fmaxf(v2.y, 0.f), fmaxf(v3.y, 0.f));
    }
}

// ---------------- after join: per-block partials of m = col_w @ h_n ----------------
// 256 blocks x 64 rows. 256 threads: d = tid&127, half = tid>>7. Deterministic.
__global__ void __launch_bounds__(256) m_kernel() {
    __shared__ float red[256];
    const int tid = threadIdx.x;
    const int d = tid & 127;
    const int half = tid >> 7;
    const int r0 = blockIdx.x * 64;
    float s = 0.f;
    #pragma unroll 8
    for (int i = 0; i < 32; ++i) {
        int r = r0 + half + 2 * i;
        s += g_colw[r] * g_hn[(size_t)r * DD + d];
    }
    red[tid] = s;
    __syncthreads();
    if (tid < 128) g_mp[blockIdx.x * DD + tid] = red[tid] + red[tid + 128];
}

// ---------------- fold partials -> m, then mm = Wm2 @ m + b ----------------
__global__ void __launch_bounds__(128) mm_kernel(const float* __restrict__ Wmb2) {
    __shared__ float m_s[DD];
    const int d = threadIdx.x;
    float acc = 0.f;
    #pragma unroll 8
    for (int b = 0; b < MB; ++b) acc += g_mp[b * DD + d];
    m_s[d] = acc;
    __syncthreads();
    float s = Wmb2[d];
    #pragma unroll 16
    for (int k = 0; k < DD; ++k) s += m_s[k] * g_WmT[k * DD + d];
    g_mm[d] = s;
}

// ---------------- out = relu(h_n + mm): pure stream, 1 float4 / thread ----------------
__global__ void __launch_bounds__(256) epi_kernel(float* __restrict__ out) {
    const int gid = blockIdx.x * 256 + threadIdx.x;   // 2048*256 = 524288 float4s
    const int c4 = gid & 31;
    float4 mv = reinterpret_cast<const float4*>(g_mm)[c4];
    float4 h  = reinterpret_cast<const float4*>(g_hn)[gid];
    float4 o;
    o.x = fmaxf(h.x + mv.x, 0.f);
    o.y = fmaxf(h.y + mv.y, 0.f);
    o.z = fmaxf(h.z + mv.z, 0.f);
    o.w = fmaxf(h.w + mv.w, 0.f);
    reinterpret_cast<float4*>(out)[gid] = o;
}

// ---------------- launch: fork side stream (prep+gemm) under colw ----------------
extern "C" void kernel_launch(void* const* d_in, const int* in_sizes, int n_in,
                              void* d_out, int out_size) {
    const int*   x    = (const int*)d_in[0];
    const int*   ea   = (const int*)d_in[1];
    const float* bond = (const float*)d_in[2];
    const float* aemb = (const float*)d_in[3];
    const float* bemb = (const float*)d_in[4];
    const float* Wi_w = (const float*)d_in[5];
    const float* Wi_b = (const float*)d_in[6];
    const float* Wm_w = (const float*)d_in[7];
    const float* Wm_b = (const float*)d_in[8];
    float* out = (float*)d_out;

    // only layer L-1 = 2 contributes to the output (h is not fed back)
    const float* Wi2  = Wi_w + 2 * DD * K2;
    const float* Wib2 = Wi_b + 2 * DD;
    const float* Wm2  = Wm_w + 2 * DD * DD;
    const float* Wmb2 = Wm_b + 2 * DD;

    // Stream/events created once on the first (uncaptured) correctness call.
    // No device memory is allocated by these APIs; captured calls replay the
    // identical fork/join every time (deterministic work).
    static cudaStream_t side = nullptr;
    static cudaEvent_t ev_fork = nullptr, ev_join = nullptr;
    if (side == nullptr) {
        cudaStreamCreateWithFlags(&side, cudaStreamNonBlocking);
        cudaEventCreateWithFlags(&ev_fork, cudaEventDisableTiming);
        cudaEventCreateWithFlags(&ev_join, cudaEventDisableTiming);
    }

    zcolw_kernel<<<64, 256>>>();

    // fork: side stream runs prep + gemm while main stream streams bond_n
    cudaEventRecord(ev_fork, 0);
    cudaStreamWaitEvent(side, ev_fork, 0);
    prep_kernel<<<128, 256, 0, side>>>(Wi2, Wm2);
    gemm_kernel<<<128, 256, 0, side>>>(x, ea, aemb, bemb, Wib2);

    colw_kernel<<<dim3(16, 64), 256>>>(bond);   // main stream, overlapped

    // join
    cudaEventRecord(ev_join, side);
    cudaStreamWaitEvent(0, ev_join, 0);

    m_kernel<<<MB, 256>>>();
    mm_kernel<<<1, 128>>>(Wmb2);
    epi_kernel<<<2048, 256>>>(out);
}

// round 7
// speedup vs baseline: 1.3287x; 1.3058x over previous
#include <cuda_runtime.h>
#include <cstdint>
#include <cstddef>

#define NN 16384          // nodes / edges
#define DD 128            // emb dim
#define K2 256            // 2*D
#define RS 132            // smem row stride (pad vs 128 to avoid conflicts)
#define KP 32             // k per phase
#define MB 256            // m-reduction blocks
#define GEMM_BLOCKS 128
#define COLW_BLOCKS 1024

// ---------------- device scratch (no allocation allowed) ----------------
__device__ float g_colw[NN];
__device__ float g_mp[MB * DD];    // per-block partials of m
__device__ float g_mm[DD];         // relu-input shift: Wm2 @ m + b
__device__ float g_hn[(size_t)NN * DD];
__device__ float g_WiT[K2 * DD];   // [k][d] = Wi2[d][k]
__device__ float g_WmT[DD * DD];   // [k][d] = Wm2[d][k]

// ---------------- f32x2 helpers (Blackwell packed fp32 FMA) ----------------
__device__ __forceinline__ unsigned long long f2pack(float lo, float hi) {
    unsigned long long r;
    asm("mov.b64 %0, {%1, %2};" : "=l"(r) : "f"(lo), "f"(hi));
    return r;
}
__device__ __forceinline__ unsigned long long ffma2(unsigned long long a,
                                                    unsigned long long b,
                                                    unsigned long long c) {
    unsigned long long d;
    asm("fma.rn.f32x2 %0, %1, %2, %3;" : "=l"(d) : "l"(a), "l"(b), "l"(c));
    return d;
}
__device__ __forceinline__ float2 f2unpack(unsigned long long v) {
    float2 f;
    asm("mov.b64 {%0, %1}, %2;" : "=f"(f.x), "=f"(f.y) : "l"(v));
    return f;
}

// ---------------- kernel 1: transpose weights + zero col_w ----------------
__global__ void __launch_bounds__(256) prep_kernel(const float* __restrict__ Wi2,
                                                   const float* __restrict__ Wm2) {
    int g = blockIdx.x * 256 + threadIdx.x;   // 128 blocks * 256 = 32768
    {   // WiT[k*128+d] = Wi2[d*256+k]
        int k = g >> 7, d = g & 127;
        g_WiT[g] = Wi2[d * K2 + k];
    }
    if (g < DD * DD) {                        // WmT[k*128+d] = Wm2[d*128+k]
        int k = g >> 7, d = g & 127;
        g_WmT[g] = Wm2[d * DD + k];
    }
    if (g < NN) g_colw[g] = 0.0f;
}

// ---------------- colw path: sum 8 consecutive rows x 32 iters (256 rows) ----------------
__device__ __forceinline__ void colw_body(int bidc, const float* __restrict__ bond) {
    const int cx = bidc & 15;                 // 16 column groups
    const int ry = bidc >> 4;                 // 64 row slices of 256 rows
    const int c4 = cx * 256 + threadIdx.x;    // float4 column index, [0,4096)
    const float4* p = reinterpret_cast<const float4*>(bond)
                      + (size_t)(ry * 256) * 4096 + c4;

    float4 s0 = make_float4(0.f, 0.f, 0.f, 0.f);
    float4 s1 = s0, s2 = s0, s3 = s0, s4 = s0, s5 = s0, s6 = s0, s7 = s0;
    for (int i = 0; i < 32; ++i) {
        float4 v0 = __ldcs(p);
        float4 v1 = __ldcs(p + 4096);
        float4 v2 = __ldcs(p + 8192);
        float4 v3 = __ldcs(p + 12288);
        float4 v4 = __ldcs(p + 16384);
        float4 v5 = __ldcs(p + 20480);
        float4 v6 = __ldcs(p + 24576);
        float4 v7 = __ldcs(p + 28672);
        p += 32768;
        s0.x += v0.x; s0.y += v0.y; s0.z += v0.z; s0.w += v0.w;
        s1.x += v1.x; s1.y += v1.y; s1.z += v1.z; s1.w += v1.w;
        s2.x += v2.x; s2.y += v2.y; s2.z += v2.z; s2.w += v2.w;
        s3.x += v3.x; s3.y += v3.y; s3.z += v3.z; s3.w += v3.w;
        s4.x += v4.x; s4.y += v4.y; s4.z += v4.z; s4.w += v4.w;
        s5.x += v5.x; s5.y += v5.y; s5.z += v5.z; s5.w += v5.w;
        s6.x += v6.x; s6.y += v6.y; s6.z += v6.z; s6.w += v6.w;
        s7.x += v7.x; s7.y += v7.y; s7.z += v7.z; s7.w += v7.w;
    }
    float sx = ((s0.x + s1.x) + (s2.x + s3.x)) + ((s4.x + s5.x) + (s6.x + s7.x));
    float sy = ((s0.y + s1.y) + (s2.y + s3.y)) + ((s4.y + s5.y) + (s6.y + s7.y));
    float sz = ((s0.z + s1.z) + (s2.z + s3.z)) + ((s4.z + s5.z) + (s6.z + s7.z));
    float sw = ((s0.w + s1.w) + (s2.w + s3.w)) + ((s4.w + s5.w) + (s6.w + s7.w));
    float* dst = &g_colw[c4 * 4];
    atomicAdd(dst + 0, sx);
    atomicAdd(dst + 1, sy);
    atomicAdd(dst + 2, sz);
    atomicAdd(dst + 3, sw);
}

// ---------------- gemm path: embeddings + h_n = relu(cat @ Wi2^T + b) ----------------
__device__ __forceinline__ void gemm_body(int bidg, float* sm,
                                          const int* __restrict__ x,
                                          const int* __restrict__ ea,
                                          const float* __restrict__ atom_emb,
                                          const float* __restrict__ bond_emb,
                                          const float* __restrict__ Wib2) {
    float* catT = sm;             // [KP][RS] : catT[k][r] = cat[row0+r][k0+k]
    float* wiT  = sm + KP * RS;   // [KP][RS] : wiT[k][d]  = Wi2[d][k0+k]

    const int tid = threadIdx.x;
    const int tx = tid & 31;      // col group (4 cols as float4)
    const int ty = tid >> 5;      // row group (16 rows)
    const int row0 = bidg * 128;

    unsigned long long acc[8][4];
    {
        float4 bias = *reinterpret_cast<const float4*>(&Wib2[tx * 4]);
        unsigned long long b0 = f2pack(bias.x, bias.x);
        unsigned long long b1 = f2pack(bias.y, bias.y);
        unsigned long long b2 = f2pack(bias.z, bias.z);
        unsigned long long b3 = f2pack(bias.w, bias.w);
        #pragma unroll
        for (int rp = 0; rp < 8; ++rp) {
            acc[rp][0] = b0; acc[rp][1] = b1; acc[rp][2] = b2; acc[rp][3] = b3;
        }
    }

    #pragma unroll 1
    for (int p = 0; p < 8; ++p) {
        __syncthreads();
        const float* src = (p < 4) ? atom_emb : bond_emb;
        const int2* idx  = (p < 4) ? reinterpret_cast<const int2*>(x)
                                   : reinterpret_cast<const int2*>(ea);
        const int kqbase = (p & 3) * 8;

        // fill catT: lanes cover consecutive r -> conflict-free STS
        #pragma unroll
        for (int it = 0; it < 4; ++it) {
            int gid = it * 256 + tid;
            int kq = gid >> 7;
            int r  = gid & 127;
            int2 ii = idx[row0 + r];
            float4 e0 = reinterpret_cast<const float4*>(src)[ii.x * 32 + kqbase + kq];
            float4 e1 = reinterpret_cast<const float4*>(src)[ii.y * 32 + kqbase + kq];
            int kb = kq * 4;
            catT[(kb + 0) * RS + r] = e0.x + e1.x;
            catT[(kb + 1) * RS + r] = e0.y + e1.y;
            catT[(kb + 2) * RS + r] = e0.z + e1.z;
            catT[(kb + 3) * RS + r] = e0.w + e1.w;
        }
        // fill wiT from pre-transposed g_WiT
        const int k0 = p * KP;
        #pragma unroll
        for (int it = 0; it < 4; ++it) {
            int gid = it * 256 + tid;
            int k  = gid >> 5;
            int d4 = gid & 31;
            float4 v = reinterpret_cast<const float4*>(g_WiT)[(k0 + k) * 32 + d4];
            *reinterpret_cast<float4*>(&wiT[k * RS + d4 * 4]) = v;
        }
        __syncthreads();

        #pragma unroll 2
        for (int k = 0; k < KP; ++k) {
            const float* ar = &catT[k * RS + ty * 16];
            ulonglong2 a01 = *reinterpret_cast<const ulonglong2*>(ar);
            ulonglong2 a23 = *reinterpret_cast<const ulonglong2*>(ar + 4);
            ulonglong2 a45 = *reinterpret_cast<const ulonglong2*>(ar + 8);
            ulonglong2 a67 = *reinterpret_cast<const ulonglong2*>(ar + 12);
            float4 b = *reinterpret_cast<const float4*>(&wiT[k * RS + tx * 4]);
            unsigned long long bb0 = f2pack(b.x, b.x);
            unsigned long long bb1 = f2pack(b.y, b.y);
            unsigned long long bb2 = f2pack(b.z, b.z);
            unsigned long long bb3 = f2pack(b.w, b.w);
            acc[0][0] = ffma2(a01.x, bb0, acc[0][0]);
            acc[0][1] = ffma2(a01.x, bb1, acc[0][1]);
            acc[0][2] = ffma2(a01.x, bb2, acc[0][2]);
            acc[0][3] = ffma2(a01.x, bb3, acc[0][3]);
            acc[1][0] = ffma2(a01.y, bb0, acc[1][0]);
            acc[1][1] = ffma2(a01.y, bb1, acc[1][1]);
            acc[1][2] = ffma2(a01.y, bb2, acc[1][2]);
            acc[1][3] = ffma2(a01.y, bb3, acc[1][3]);
            acc[2][0] = ffma2(a23.x, bb0, acc[2][0]);
            acc[2][1] = ffma2(a23.x, bb1, acc[2][1]);
            acc[2][2] = ffma2(a23.x, bb2, acc[2][2]);
            acc[2][3] = ffma2(a23.x, bb3, acc[2][3]);
            acc[3][0] = ffma2(a23.y, bb0, acc[3][0]);
            acc[3][1] = ffma2(a23.y, bb1, acc[3][1]);
            acc[3][2] = ffma2(a23.y, bb2, acc[3][2]);
            acc[3][3] = ffma2(a23.y, bb3, acc[3][3]);
            acc[4][0] = ffma2(a45.x, bb0, acc[4][0]);
            acc[4][1] = ffma2(a45.x, bb1, acc[4][1]);
            acc[4][2] = ffma2(a45.x, bb2, acc[4][2]);
            acc[4][3] = ffma2(a45.x, bb3, acc[4][3]);
            acc[5][0] = ffma2(a45.y, bb0, acc[5][0]);
            acc[5][1] = ffma2(a45.y, bb1, acc[5][1]);
            acc[5][2] = ffma2(a45.y, bb2, acc[5][2]);
            acc[5][3] = ffma2(a45.y, bb3, acc[5][3]);
            acc[6][0] = ffma2(a67.x, bb0, acc[6][0]);
            acc[6][1] = ffma2(a67.x, bb1, acc[6][1]);
            acc[6][2] = ffma2(a67.x, bb2, acc[6][2]);
            acc[6][3] = ffma2(a67.x, bb3, acc[6][3]);
            acc[7][0] = ffma2(a67.y, bb0, acc[7][0]);
            acc[7][1] = ffma2(a67.y, bb1, acc[7][1]);
            acc[7][2] = ffma2(a67.y, bb2, acc[7][2]);
            acc[7][3] = ffma2(a67.y, bb3, acc[7][3]);
        }
    }

    // epilogue: relu + store h_n
    #pragma unroll
    for (int rp = 0; rp < 8; ++rp) {
        float2 v0 = f2unpack(acc[rp][0]);
        float2 v1 = f2unpack(acc[rp][1]);
        float2 v2 = f2unpack(acc[rp][2]);
        float2 v3 = f2unpack(acc[rp][3]);
        int r = row0 + ty * 16 + rp * 2;
        *reinterpret_cast<float4*>(&g_hn[(size_t)r * DD + tx * 4]) =
            make_float4(fmaxf(v0.x, 0.f), fmaxf(v1.x, 0.f),
                        fmaxf(v2.x, 0.f), fmaxf(v3.x, 0.f));
        *reinterpret_cast<float4*>(&g_hn[(size_t)(r + 1) * DD + tx * 4]) =
            make_float4(fmaxf(v0.y, 0.f), fmaxf(v1.y, 0.f),
                        fmaxf(v2.y, 0.f), fmaxf(v3.y, 0.f));
    }
}

// ---------------- fused kernel: gemm blocks [0,128), colw blocks [128,1152) ----------------
__global__ void __launch_bounds__(256) fused_kernel(const float* __restrict__ bond,
                                                    const int* __restrict__ x,
                                                    const int* __restrict__ ea,
                                                    const float* __restrict__ atom_emb,
                                                    const float* __restrict__ bond_emb,
                                                    const float* __restrict__ Wib2) {
    __shared__ __align__(16) float sm[2 * KP * RS];   // 33 KB (gemm path only)
    if (blockIdx.x < GEMM_BLOCKS) {
        gemm_body(blockIdx.x, sm, x, ea, atom_emb, bond_emb, Wib2);
    } else {
        colw_body(blockIdx.x - GEMM_BLOCKS, bond);
    }
}

// ---------------- per-block partials of m = col_w @ h_n (deterministic) ----------------
__global__ void __launch_bounds__(256) m_kernel() {
    __shared__ float red[256];
    const int tid = threadIdx.x;
    const int d = tid & 127;
    const int half = tid >> 7;
    const int r0 = blockIdx.x * 64;
    float s = 0.f;
    #pragma unroll 8
    for (int i = 0; i < 32; ++i) {
        int r = r0 + half + 2 * i;
        s += g_colw[r] * g_hn[(size_t)r * DD + d];
    }
    red[tid] = s;
    __syncthreads();
    if (tid < 128) g_mp[blockIdx.x * DD + tid] = red[tid] + red[tid + 128];
}

// ---------------- fold partials -> m, then mm = Wm2 @ m + b ----------------
__global__ void __launch_bounds__(128) mm_kernel(const float* __restrict__ Wmb2) {
    __shared__ float m_s[DD];
    const int d = threadIdx.x;
    float acc = 0.f;
    #pragma unroll 8
    for (int b = 0; b < MB; ++b) acc += g_mp[b * DD + d];
    m_s[d] = acc;
    __syncthreads();
    float s = Wmb2[d];
    #pragma unroll 16
    for (int k = 0; k < DD; ++k) s += m_s[k] * g_WmT[k * DD + d];
    g_mm[d] = s;
}

// ---------------- out = relu(h_n + mm): pure stream, 1 float4 / thread ----------------
__global__ void __launch_bounds__(256) epi_kernel(float* __restrict__ out) {
    const int gid = blockIdx.x * 256 + threadIdx.x;   // 2048*256 = 524288 float4s
    const int c4 = gid & 31;
    float4 mv = reinterpret_cast<const float4*>(g_mm)[c4];
    float4 h  = reinterpret_cast<const float4*>(g_hn)[gid];
    float4 o;
    o.x = fmaxf(h.x + mv.x, 0.f);
    o.y = fmaxf(h.y + mv.y, 0.f);
    o.z = fmaxf(h.z + mv.z, 0.f);
    o.w = fmaxf(h.w + mv.w, 0.f);
    reinterpret_cast<float4*>(out)[gid] = o;
}

// ---------------- launch: single stream, overlap is structural ----------------
extern "C" void kernel_launch(void* const* d_in, const int* in_sizes, int n_in,
                              void* d_out, int out_size) {
    const int*   x    = (const int*)d_in[0];
    const int*   ea   = (const int*)d_in[1];
    const float* bond = (const float*)d_in[2];
    const float* aemb = (const float*)d_in[3];
    const float* bemb = (const float*)d_in[4];
    const float* Wi_w = (const float*)d_in[5];
    const float* Wi_b = (const float*)d_in[6];
    const float* Wm_w = (const float*)d_in[7];
    const float* Wm_b = (const float*)d_in[8];
    float* out = (float*)d_out;

    // only layer L-1 = 2 contributes to the output (h is not fed back)
    const float* Wi2  = Wi_w + 2 * DD * K2;
    const float* Wib2 = Wi_b + 2 * DD;
    const float* Wm2  = Wm_w + 2 * DD * DD;
    const float* Wmb2 = Wm_b + 2 * DD;

    prep_kernel<<<128, 256>>>(Wi2, Wm2);
    fused_kernel<<<GEMM_BLOCKS + COLW_BLOCKS, 256>>>(bond, x, ea, aemb, bemb, Wib2);
    m_kernel<<<MB, 256>>>();
    mm_kernel<<<1, 128>>>(Wmb2);
    epi_kernel<<<2048, 256>>>(out);
}

// round 8
// speedup vs baseline: 1.3613x; 1.0246x over previous
#include <cuda_runtime.h>
#include <cstdint>
#include <cstddef>

#define NN 16384          // nodes / edges
#define DD 128            // emb dim
#define K2 256            // 2*D
#define RS 132            // smem row stride (pad vs 128 to avoid conflicts)
#define KP 32             // k per phase
#define MB 256            // m-reduction blocks
#define GEMM_BLOCKS 128
#define COLW_BLOCKS 1024

// ---------------- device scratch (no allocation allowed) ----------------
__device__ float g_colw[NN];
__device__ float g_mp[MB * DD];    // per-block partials of m
__device__ float g_mm[DD];         // relu-input shift: Wm2 @ m + b
__device__ float g_hn[(size_t)NN * DD];
__device__ float g_WiT[K2 * DD];   // [k][d] = Wi2[d][k]

// ---------------- f32x2 helpers (Blackwell packed fp32 FMA) ----------------
__device__ __forceinline__ unsigned long long f2pack(float lo, float hi) {
    unsigned long long r;
    asm("mov.b64 %0, {%1, %2};" : "=l"(r) : "f"(lo), "f"(hi));
    return r;
}
__device__ __forceinline__ unsigned long long ffma2(unsigned long long a,
                                                    unsigned long long b,
                                                    unsigned long long c) {
    unsigned long long d;
    asm("fma.rn.f32x2 %0, %1, %2, %3;" : "=l"(d) : "l"(a), "l"(b), "l"(c));
    return d;
}
__device__ __forceinline__ float2 f2unpack(unsigned long long v) {
    float2 f;
    asm("mov.b64 {%0, %1}, %2;" : "=f"(f.x), "=f"(f.y) : "l"(v));
    return f;
}

// ---------------- kernel 1: transpose Wi + zero col_w ----------------
__global__ void __launch_bounds__(256) prep_kernel(const float* __restrict__ Wi2) {
    int g = blockIdx.x * 256 + threadIdx.x;   // 128 blocks * 256 = 32768
    {   // WiT[k*128+d] = Wi2[d*256+k]
        int k = g >> 7, d = g & 127;
        g_WiT[g] = Wi2[d * K2 + k];
    }
    if (g < NN) g_colw[g] = 0.0f;
}

// ---------------- colw path: sum 8 consecutive rows x 32 iters (256 rows) ----------------
__device__ __forceinline__ void colw_body(int bidc, const float* __restrict__ bond) {
    const int cx = bidc & 15;                 // 16 column groups
    const int ry = bidc >> 4;                 // 64 row slices of 256 rows
    const int c4 = cx * 256 + threadIdx.x;    // float4 column index, [0,4096)
    const float4* p = reinterpret_cast<const float4*>(bond)
                      + (size_t)(ry * 256) * 4096 + c4;

    float4 s0 = make_float4(0.f, 0.f, 0.f, 0.f);
    float4 s1 = s0, s2 = s0, s3 = s0, s4 = s0, s5 = s0, s6 = s0, s7 = s0;
    for (int i = 0; i < 32; ++i) {
        float4 v0 = __ldcs(p);
        float4 v1 = __ldcs(p + 4096);
        float4 v2 = __ldcs(p + 8192);
        float4 v3 = __ldcs(p + 12288);
        float4 v4 = __ldcs(p + 16384);
        float4 v5 = __ldcs(p + 20480);
        float4 v6 = __ldcs(p + 24576);
        float4 v7 = __ldcs(p + 28672);
        p += 32768;
        s0.x += v0.x; s0.y += v0.y; s0.z += v0.z; s0.w += v0.w;
        s1.x += v1.x; s1.y += v1.y; s1.z += v1.z; s1.w += v1.w;
        s2.x += v2.x; s2.y += v2.y; s2.z += v2.z; s2.w += v2.w;
        s3.x += v3.x; s3.y += v3.y; s3.z += v3.z; s3.w += v3.w;
        s4.x += v4.x; s4.y += v4.y; s4.z += v4.z; s4.w += v4.w;
        s5.x += v5.x; s5.y += v5.y; s5.z += v5.z; s5.w += v5.w;
        s6.x += v6.x; s6.y += v6.y; s6.z += v6.z; s6.w += v6.w;
        s7.x += v7.x; s7.y += v7.y; s7.z += v7.z; s7.w += v7.w;
    }
    float sx = ((s0.x + s1.x) + (s2.x + s3.x)) + ((s4.x + s5.x) + (s6.x + s7.x));
    float sy = ((s0.y + s1.y) + (s2.y + s3.y)) + ((s4.y + s5.y) + (s6.y + s7.y));
    float sz = ((s0.z + s1.z) + (s2.z + s3.z)) + ((s4.z + s5.z) + (s6.z + s7.z));
    float sw = ((s0.w + s1.w) + (s2.w + s3.w)) + ((s4.w + s5.w) + (s6.w + s7.w));
    float* dst = &g_colw[c4 * 4];
    atomicAdd(dst + 0, sx);
    atomicAdd(dst + 1, sy);
    atomicAdd(dst + 2, sz);
    atomicAdd(dst + 3, sw);
}

// ---------------- gemm path: embeddings + h_n = relu(cat @ Wi2^T + b) ----------------
__device__ __forceinline__ void gemm_body(int bidg, float* sm,
                                          const int* __restrict__ x,
                                          const int* __restrict__ ea,
                                          const float* __restrict__ atom_emb,
                                          const float* __restrict__ bond_emb,
                                          const float* __restrict__ Wib2) {
    float* catT = sm;             // [KP][RS] : catT[k][r] = cat[row0+r][k0+k]
    float* wiT  = sm + KP * RS;   // [KP][RS] : wiT[k][d]  = Wi2[d][k0+k]

    const int tid = threadIdx.x;
    const int tx = tid & 31;      // col group (4 cols as float4)
    const int ty = tid >> 5;      // row group (16 rows)
    const int row0 = bidg * 128;

    unsigned long long acc[8][4];
    {
        float4 bias = *reinterpret_cast<const float4*>(&Wib2[tx * 4]);
        unsigned long long b0 = f2pack(bias.x, bias.x);
        unsigned long long b1 = f2pack(bias.y, bias.y);
        unsigned long long b2 = f2pack(bias.z, bias.z);
        unsigned long long b3 = f2pack(bias.w, bias.w);
        #pragma unroll
        for (int rp = 0; rp < 8; ++rp) {
            acc[rp][0] = b0; acc[rp][1] = b1; acc[rp][2] = b2; acc[rp][3] = b3;
        }
    }

    #pragma unroll 1
    for (int p = 0; p < 8; ++p) {
        __syncthreads();
        const float* src = (p < 4) ? atom_emb : bond_emb;
        const int2* idx  = (p < 4) ? reinterpret_cast<const int2*>(x)
                                   : reinterpret_cast<const int2*>(ea);
        const int kqbase = (p & 3) * 8;

        // fill catT: lanes cover consecutive r -> conflict-free STS
        #pragma unroll
        for (int it = 0; it < 4; ++it) {
            int gid = it * 256 + tid;
            int kq = gid >> 7;
            int r  = gid & 127;
            int2 ii = idx[row0 + r];
            float4 e0 = reinterpret_cast<const float4*>(src)[ii.x * 32 + kqbase + kq];
            float4 e1 = reinterpret_cast<const float4*>(src)[ii.y * 32 + kqbase + kq];
            int kb = kq * 4;
            catT[(kb + 0) * RS + r] = e0.x + e1.x;
            catT[(kb + 1) * RS + r] = e0.y + e1.y;
            catT[(kb + 2) * RS + r] = e0.z + e1.z;
            catT[(kb + 3) * RS + r] = e0.w + e1.w;
        }
        // fill wiT from pre-transposed g_WiT
        const int k0 = p * KP;
        #pragma unroll
        for (int it = 0; it < 4; ++it) {
            int gid = it * 256 + tid;
            int k  = gid >> 5;
            int d4 = gid & 31;
            float4 v = reinterpret_cast<const float4*>(g_WiT)[(k0 + k) * 32 + d4];
            *reinterpret_cast<float4*>(&wiT[k * RS + d4 * 4]) = v;
        }
        __syncthreads();

        #pragma unroll 2
        for (int k = 0; k < KP; ++k) {
            const float* ar = &catT[k * RS + ty * 16];
            ulonglong2 a01 = *reinterpret_cast<const ulonglong2*>(ar);
            ulonglong2 a23 = *reinterpret_cast<const ulonglong2*>(ar + 4);
            ulonglong2 a45 = *reinterpret_cast<const ulonglong2*>(ar + 8);
            ulonglong2 a67 = *reinterpret_cast<const ulonglong2*>(ar + 12);
            float4 b = *reinterpret_cast<const float4*>(&wiT[k * RS + tx * 4]);
            unsigned long long bb0 = f2pack(b.x, b.x);
            unsigned long long bb1 = f2pack(b.y, b.y);
            unsigned long long bb2 = f2pack(b.z, b.z);
            unsigned long long bb3 = f2pack(b.w, b.w);
            acc[0][0] = ffma2(a01.x, bb0, acc[0][0]);
            acc[0][1] = ffma2(a01.x, bb1, acc[0][1]);
            acc[0][2] = ffma2(a01.x, bb2, acc[0][2]);
            acc[0][3] = ffma2(a01.x, bb3, acc[0][3]);
            acc[1][0] = ffma2(a01.y, bb0, acc[1][0]);
            acc[1][1] = ffma2(a01.y, bb1, acc[1][1]);
            acc[1][2] = ffma2(a01.y, bb2, acc[1][2]);
            acc[1][3] = ffma2(a01.y, bb3, acc[1][3]);
            acc[2][0] = ffma2(a23.x, bb0, acc[2][0]);
            acc[2][1] = ffma2(a23.x, bb1, acc[2][1]);
            acc[2][2] = ffma2(a23.x, bb2, acc[2][2]);
            acc[2][3] = ffma2(a23.x, bb3, acc[2][3]);
            acc[3][0] = ffma2(a23.y, bb0, acc[3][0]);
            acc[3][1] = ffma2(a23.y, bb1, acc[3][1]);
            acc[3][2] = ffma2(a23.y, bb2, acc[3][2]);
            acc[3][3] = ffma2(a23.y, bb3, acc[3][3]);
            acc[4][0] = ffma2(a45.x, bb0, acc[4][0]);
            acc[4][1] = ffma2(a45.x, bb1, acc[4][1]);
            acc[4][2] = ffma2(a45.x, bb2, acc[4][2]);
            acc[4][3] = ffma2(a45.x, bb3, acc[4][3]);
            acc[5][0] = ffma2(a45.y, bb0, acc[5][0]);
            acc[5][1] = ffma2(a45.y, bb1, acc[5][1]);
            acc[5][2] = ffma2(a45.y, bb2, acc[5][2]);
            acc[5][3] = ffma2(a45.y, bb3, acc[5][3]);
            acc[6][0] = ffma2(a67.x, bb0, acc[6][0]);
            acc[6][1] = ffma2(a67.x, bb1, acc[6][1]);
            acc[6][2] = ffma2(a67.x, bb2, acc[6][2]);
            acc[6][3] = ffma2(a67.x, bb3, acc[6][3]);
            acc[7][0] = ffma2(a67.y, bb0, acc[7][0]);
            acc[7][1] = ffma2(a67.y, bb1, acc[7][1]);
            acc[7][2] = ffma2(a67.y, bb2, acc[7][2]);
            acc[7][3] = ffma2(a67.y, bb3, acc[7][3]);
        }
    }

    // epilogue: relu + store h_n
    #pragma unroll
    for (int rp = 0; rp < 8; ++rp) {
        float2 v0 = f2unpack(acc[rp][0]);
        float2 v1 = f2unpack(acc[rp][1]);
        float2 v2 = f2unpack(acc[rp][2]);
        float2 v3 = f2unpack(acc[rp][3]);
        int r = row0 + ty * 16 + rp * 2;
        *reinterpret_cast<float4*>(&g_hn[(size_t)r * DD + tx * 4]) =
            make_float4(fmaxf(v0.x, 0.f), fmaxf(v1.x, 0.f),
                        fmaxf(v2.x, 0.f), fmaxf(v3.x, 0.f));
        *reinterpret_cast<float4*>(&g_hn[(size_t)(r + 1) * DD + tx * 4]) =
            make_float4(fmaxf(v0.y, 0.f), fmaxf(v1.y, 0.f),
                        fmaxf(v2.y, 0.f), fmaxf(v3.y, 0.f));
    }
}

// ---------------- fused kernel: gemm blocks [0,128), colw blocks [128,1152) ----------------
__global__ void __launch_bounds__(256) fused_kernel(const float* __restrict__ bond,
                                                    const int* __restrict__ x,
                                                    const int* __restrict__ ea,
                                                    const float* __restrict__ atom_emb,
                                                    const float* __restrict__ bond_emb,
                                                    const float* __restrict__ Wib2) {
    __shared__ __align__(16) float sm[2 * KP * RS];   // 33 KB (gemm path only)
    if (blockIdx.x < GEMM_BLOCKS) {
        gemm_body(blockIdx.x, sm, x, ea, atom_emb, bond_emb, Wib2);
    } else {
        colw_body(blockIdx.x - GEMM_BLOCKS, bond);
    }
}

// ---------------- per-block partials of m = col_w @ h_n (deterministic) ----------------
__global__ void __launch_bounds__(256) m_kernel() {
    __shared__ float red[256];
    const int tid = threadIdx.x;
    const int d = tid & 127;
    const int half = tid >> 7;
    const int r0 = blockIdx.x * 64;
    float s = 0.f;
    #pragma unroll 8
    for (int i = 0; i < 32; ++i) {
        int r = r0 + half + 2 * i;
        s += g_colw[r] * g_hn[(size_t)r * DD + d];
    }
    red[tid] = s;
    __syncthreads();
    if (tid < 128) g_mp[blockIdx.x * DD + tid] = red[tid] + red[tid + 128];
}

// ---------------- mm[d] = Wmb2[d] + sum_k (sum_b mp[b][k]) * Wm2[d][k] ----------------
// 128 blocks (one per output d), 128 threads (one per k). Fold is redundant
// across blocks but fully parallel, coalesced, L2-resident. Wm2 row d is
// contiguous so no transpose needed. Deterministic (fixed reduction order).
__global__ void __launch_bounds__(128) mm_kernel(const float* __restrict__ Wm2,
                                                 const float* __restrict__ Wmb2) {
    __shared__ float red[128];
    const int d = blockIdx.x;
    const int k = threadIdx.x;
    float mk = 0.f;
    #pragma unroll 16
    for (int b = 0; b < MB; ++b) mk += g_mp[b * DD + k];
    red[k] = mk * Wm2[d * DD + k];
    __syncthreads();
    if (k < 64) red[k] += red[k + 64];
    __syncthreads();
    if (k < 32) {
        float v = red[k] + red[k + 32];
        #pragma unroll
        for (int o = 16; o > 0; o >>= 1) v += __shfl_down_sync(0xffffffffu, v, o);
        if (k == 0) g_mm[d] = Wmb2[d] + v;
    }
}

// ---------------- out = relu(h_n + mm): pure stream, 1 float4 / thread ----------------
__global__ void __launch_bounds__(256) epi_kernel(float* __restrict__ out) {
    const int gid = blockIdx.x * 256 + threadIdx.x;   // 2048*256 = 524288 float4s
    const int c4 = gid & 31;
    float4 mv = reinterpret_cast<const float4*>(g_mm)[c4];
    float4 h  = reinterpret_cast<const float4*>(g_hn)[gid];
    float4 o;
    o.x = fmaxf(h.x + mv.x, 0.f);
    o.y = fmaxf(h.y + mv.y, 0.f);
    o.z = fmaxf(h.z + mv.z, 0.f);
    o.w = fmaxf(h.w + mv.w, 0.f);
    reinterpret_cast<float4*>(out)[gid] = o;
}

// ---------------- launch: single stream, overlap is structural ----------------
extern "C" void kernel_launch(void* const* d_in, const int* in_sizes, int n_in,
                              void* d_out, int out_size) {
    const int*   x    = (const int*)d_in[0];
    const int*   ea   = (const int*)d_in[1];
    const float* bond = (const float*)d_in[2];
    const float* aemb = (const float*)d_in[3];
    const float* bemb = (const float*)d_in[4];
    const float* Wi_w = (const float*)d_in[5];
    const float* Wi_b = (const float*)d_in[6];
    const float* Wm_w = (const float*)d_in[7];
    const float* Wm_b = (const float*)d_in[8];
    float* out = (float*)d_out;

    // only layer L-1 = 2 contributes to the output (h is not fed back)
    const float* Wi2  = Wi_w + 2 * DD * K2;
    const float* Wib2 = Wi_b + 2 * DD;
    const float* Wm2  = Wm_w + 2 * DD * DD;
    const float* Wmb2 = Wm_b + 2 * DD;

    prep_kernel<<<128, 256>>>(Wi2);
    fused_kernel<<<GEMM_BLOCKS + COLW_BLOCKS, 256>>>(bond, x, ea, aemb, bemb, Wib2);
    m_kernel<<<MB, 256>>>();
    mm_kernel<<<128, 128>>>(Wm2, Wmb2);
    epi_kernel<<<2048, 256>>>(out);
}

// round 9
// speedup vs baseline: 1.3919x; 1.0225x over previous
#include <cuda_runtime.h>
#include <cstdint>
#include <cstddef>

#define NN 16384          // nodes / edges
#define DD 128            // emb dim
#define K2 256            // 2*D
#define RS 132            // smem row stride (pad vs 128 to avoid conflicts)
#define KP 32             // k per phase
#define GEMM_BLOCKS 128
#define COLW_BLOCKS 1024

// ---------------- device scratch (no allocation allowed) ----------------
__device__ float g_colw[NN];
__device__ float g_m[DD];          // m = col_w @ h_n  (atomic accumulation)
__device__ float g_mm[DD];         // relu-input shift: Wm2 @ m + b
__device__ float g_hn[(size_t)NN * DD];
__device__ float g_WiT[K2 * DD];   // [k][d] = Wi2[d][k]

// ---------------- f32x2 helpers (Blackwell packed fp32 FMA) ----------------
__device__ __forceinline__ unsigned long long f2pack(float lo, float hi) {
    unsigned long long r;
    asm("mov.b64 %0, {%1, %2};" : "=l"(r) : "f"(lo), "f"(hi));
    return r;
}
__device__ __forceinline__ unsigned long long ffma2(unsigned long long a,
                                                    unsigned long long b,
                                                    unsigned long long c) {
    unsigned long long d;
    asm("fma.rn.f32x2 %0, %1, %2, %3;" : "=l"(d) : "l"(a), "l"(b), "l"(c));
    return d;
}
__device__ __forceinline__ float2 f2unpack(unsigned long long v) {
    float2 f;
    asm("mov.b64 {%0, %1}, %2;" : "=f"(f.x), "=f"(f.y) : "l"(v));
    return f;
}

// ---------------- kernel 1: transpose Wi + zero col_w and m ----------------
__global__ void __launch_bounds__(256) prep_kernel(const float* __restrict__ Wi2) {
    int g = blockIdx.x * 256 + threadIdx.x;   // 128 blocks * 256 = 32768
    {   // WiT[k*128+d] = Wi2[d*256+k]
        int k = g >> 7, d = g & 127;
        g_WiT[g] = Wi2[d * K2 + k];
    }
    if (g < NN) g_colw[g] = 0.0f;
    if (g < DD) g_m[g] = 0.0f;
}

// ---------------- colw path: sum 8 consecutive rows x 32 iters (256 rows) ----------------
__device__ __forceinline__ void colw_body(int bidc, const float* __restrict__ bond) {
    const int cx = bidc & 15;                 // 16 column groups
    const int ry = bidc >> 4;                 // 64 row slices of 256 rows
    const int c4 = cx * 256 + threadIdx.x;    // float4 column index, [0,4096)
    const float4* p = reinterpret_cast<const float4*>(bond)
                      + (size_t)(ry * 256) * 4096 + c4;

    float4 s0 = make_float4(0.f, 0.f, 0.f, 0.f);
    float4 s1 = s0, s2 = s0, s3 = s0, s4 = s0, s5 = s0, s6 = s0, s7 = s0;
    for (int i = 0; i < 32; ++i) {
        float4 v0 = __ldcs(p);
        float4 v1 = __ldcs(p + 4096);
        float4 v2 = __ldcs(p + 8192);
        float4 v3 = __ldcs(p + 12288);
        float4 v4 = __ldcs(p + 16384);
        float4 v5 = __ldcs(p + 20480);
        float4 v6 = __ldcs(p + 24576);
        float4 v7 = __ldcs(p + 28672);
        p += 32768;
        s0.x += v0.x; s0.y += v0.y; s0.z += v0.z; s0.w += v0.w;
        s1.x += v1.x; s1.y += v1.y; s1.z += v1.z; s1.w += v1.w;
        s2.x += v2.x; s2.y += v2.y; s2.z += v2.z; s2.w += v2.w;
        s3.x += v3.x; s3.y += v3.y; s3.z += v3.z; s3.w += v3.w;
        s4.x += v4.x; s4.y += v4.y; s4.z += v4.z; s4.w += v4.w;
        s5.x += v5.x; s5.y += v5.y; s5.z += v5.z; s5.w += v5.w;
        s6.x += v6.x; s6.y += v6.y; s6.z += v6.z; s6.w += v6.w;
        s7.x += v7.x; s7.y += v7.y; s7.z += v7.z; s7.w += v7.w;
    }
    float sx = ((s0.x + s1.x) + (s2.x + s3.x)) + ((s4.x + s5.x) + (s6.x + s7.x));
    float sy = ((s0.y + s1.y) + (s2.y + s3.y)) + ((s4.y + s5.y) + (s6.y + s7.y));
    float sz = ((s0.z + s1.z) + (s2.z + s3.z)) + ((s4.z + s5.z) + (s6.z + s7.z));
    float sw = ((s0.w + s1.w) + (s2.w + s3.w)) + ((s4.w + s5.w) + (s6.w + s7.w));
    float* dst = &g_colw[c4 * 4];
    atomicAdd(dst + 0, sx);
    atomicAdd(dst + 1, sy);
    atomicAdd(dst + 2, sz);
    atomicAdd(dst + 3, sw);
}

// ---------------- gemm path: embeddings + h_n = relu(cat @ Wi2^T + b) ----------------
__device__ __forceinline__ void gemm_body(int bidg, float* sm,
                                          const int* __restrict__ x,
                                          const int* __restrict__ ea,
                                          const float* __restrict__ atom_emb,
                                          const float* __restrict__ bond_emb,
                                          const float* __restrict__ Wib2) {
    float* catT = sm;             // [KP][RS] : catT[k][r] = cat[row0+r][k0+k]
    float* wiT  = sm + KP * RS;   // [KP][RS] : wiT[k][d]  = Wi2[d][k0+k]

    const int tid = threadIdx.x;
    const int tx = tid & 31;      // col group (4 cols as float4)
    const int ty = tid >> 5;      // row group (16 rows)
    const int row0 = bidg * 128;

    unsigned long long acc[8][4];
    {
        float4 bias = *reinterpret_cast<const float4*>(&Wib2[tx * 4]);
        unsigned long long b0 = f2pack(bias.x, bias.x);
        unsigned long long b1 = f2pack(bias.y, bias.y);
        unsigned long long b2 = f2pack(bias.z, bias.z);
        unsigned long long b3 = f2pack(bias.w, bias.w);
        #pragma unroll
        for (int rp = 0; rp < 8; ++rp) {
            acc[rp][0] = b0; acc[rp][1] = b1; acc[rp][2] = b2; acc[rp][3] = b3;
        }
    }

    #pragma unroll 1
    for (int p = 0; p < 8; ++p) {
        __syncthreads();
        const float* src = (p < 4) ? atom_emb : bond_emb;
        const int2* idx  = (p < 4) ? reinterpret_cast<const int2*>(x)
                                   : reinterpret_cast<const int2*>(ea);
        const int kqbase = (p & 3) * 8;

        // fill catT: lanes cover consecutive r -> conflict-free STS
        #pragma unroll
        for (int it = 0; it < 4; ++it) {
            int gid = it * 256 + tid;
            int kq = gid >> 7;
            int r  = gid & 127;
            int2 ii = idx[row0 + r];
            float4 e0 = reinterpret_cast<const float4*>(src)[ii.x * 32 + kqbase + kq];
            float4 e1 = reinterpret_cast<const float4*>(src)[ii.y * 32 + kqbase + kq];
            int kb = kq * 4;
            catT[(kb + 0) * RS + r] = e0.x + e1.x;
            catT[(kb + 1) * RS + r] = e0.y + e1.y;
            catT[(kb + 2) * RS + r] = e0.z + e1.z;
            catT[(kb + 3) * RS + r] = e0.w + e1.w;
        }
        // fill wiT from pre-transposed g_WiT
        const int k0 = p * KP;
        #pragma unroll
        for (int it = 0; it < 4; ++it) {
            int gid = it * 256 + tid;
            int k  = gid >> 5;
            int d4 = gid & 31;
            float4 v = reinterpret_cast<const float4*>(g_WiT)[(k0 + k) * 32 + d4];
            *reinterpret_cast<float4*>(&wiT[k * RS + d4 * 4]) = v;
        }
        __syncthreads();

        #pragma unroll 2
        for (int k = 0; k < KP; ++k) {
            const float* ar = &catT[k * RS + ty * 16];
            ulonglong2 a01 = *reinterpret_cast<const ulonglong2*>(ar);
            ulonglong2 a23 = *reinterpret_cast<const ulonglong2*>(ar + 4);
            ulonglong2 a45 = *reinterpret_cast<const ulonglong2*>(ar + 8);
            ulonglong2 a67 = *reinterpret_cast<const ulonglong2*>(ar + 12);
            float4 b = *reinterpret_cast<const float4*>(&wiT[k * RS + tx * 4]);
            unsigned long long bb0 = f2pack(b.x, b.x);
            unsigned long long bb1 = f2pack(b.y, b.y);
            unsigned long long bb2 = f2pack(b.z, b.z);
            unsigned long long bb3 = f2pack(b.w, b.w);
            acc[0][0] = ffma2(a01.x, bb0, acc[0][0]);
            acc[0][1] = ffma2(a01.x, bb1, acc[0][1]);
            acc[0][2] = ffma2(a01.x, bb2, acc[0][2]);
            acc[0][3] = ffma2(a01.x, bb3, acc[0][3]);
            acc[1][0] = ffma2(a01.y, bb0, acc[1][0]);
            acc[1][1] = ffma2(a01.y, bb1, acc[1][1]);
            acc[1][2] = ffma2(a01.y, bb2, acc[1][2]);
            acc[1][3] = ffma2(a01.y, bb3, acc[1][3]);
            acc[2][0] = ffma2(a23.x, bb0, acc[2][0]);
            acc[2][1] = ffma2(a23.x, bb1, acc[2][1]);
            acc[2][2] = ffma2(a23.x, bb2, acc[2][2]);
            acc[2][3] = ffma2(a23.x, bb3, acc[2][3]);
            acc[3][0] = ffma2(a23.y, bb0, acc[3][0]);
            acc[3][1] = ffma2(a23.y, bb1, acc[3][1]);
            acc[3][2] = ffma2(a23.y, bb2, acc[3][2]);
            acc[3][3] = ffma2(a23.y, bb3, acc[3][3]);
            acc[4][0] = ffma2(a45.x, bb0, acc[4][0]);
            acc[4][1] = ffma2(a45.x, bb1, acc[4][1]);
            acc[4][2] = ffma2(a45.x, bb2, acc[4][2]);
            acc[4][3] = ffma2(a45.x, bb3, acc[4][3]);
            acc[5][0] = ffma2(a45.y, bb0, acc[5][0]);
            acc[5][1] = ffma2(a45.y, bb1, acc[5][1]);
            acc[5][2] = ffma2(a45.y, bb2, acc[5][2]);
            acc[5][3] = ffma2(a45.y, bb3, acc[5][3]);
            acc[6][0] = ffma2(a67.x, bb0, acc[6][0]);
            acc[6][1] = ffma2(a67.x, bb1, acc[6][1]);
            acc[6][2] = ffma2(a67.x, bb2, acc[6][2]);
            acc[6][3] = ffma2(a67.x, bb3, acc[6][3]);
            acc[7][0] = ffma2(a67.y, bb0, acc[7][0]);
            acc[7][1] = ffma2(a67.y, bb1, acc[7][1]);
            acc[7][2] = ffma2(a67.y, bb2, acc[7][2]);
            acc[7][3] = ffma2(a67.y, bb3, acc[7][3]);
        }
    }

    // epilogue: relu + store h_n
    #pragma unroll
    for (int rp = 0; rp < 8; ++rp) {
        float2 v0 = f2unpack(acc[rp][0]);
        float2 v1 = f2unpack(acc[rp][1]);
        float2 v2 = f2unpack(acc[rp][2]);
        float2 v3 = f2unpack(acc[rp][3]);
        int r = row0 + ty * 16 + rp * 2;
        *reinterpret_cast<float4*>(&g_hn[(size_t)r * DD + tx * 4]) =
            make_float4(fmaxf(v0.x, 0.f), fmaxf(v1.x, 0.f),
                        fmaxf(v2.x, 0.f), fmaxf(v3.x, 0.f));
        *reinterpret_cast<float4*>(&g_hn[(size_t)(r + 1) * DD + tx * 4]) =
            make_float4(fmaxf(v0.y, 0.f), fmaxf(v1.y, 0.f),
                        fmaxf(v2.y, 0.f), fmaxf(v3.y, 0.f));
    }
}

// ---------------- fused kernel: gemm blocks [0,128), colw blocks [128,1152) ----------------
__global__ void __launch_bounds__(256) fused_kernel(const float* __restrict__ bond,
                                                    const int* __restrict__ x,
                                                    const int* __restrict__ ea,
                                                    const float* __restrict__ atom_emb,
                                                    const float* __restrict__ bond_emb,
                                                    const float* __restrict__ Wib2) {
    __shared__ __align__(16) float sm[2 * KP * RS];   // 33 KB (gemm path only)
    if (blockIdx.x < GEMM_BLOCKS) {
        gemm_body(blockIdx.x, sm, x, ea, atom_emb, bond_emb, Wib2);
    } else {
        colw_body(blockIdx.x - GEMM_BLOCKS, bond);
    }
}

// ---------------- m[d] += sum_r col_w[r] * h_n[r][d] over this block's rows ----------------
// 128 blocks x 128 rows each; per-block smem reduce then one atomic per d.
__global__ void __launch_bounds__(256) m_kernel() {
    __shared__ float red[256];
    const int tid = threadIdx.x;
    const int d = tid & 127;
    const int half = tid >> 7;
    const int r0 = blockIdx.x * 128;
    float s = 0.f;
    #pragma unroll 16
    for (int i = 0; i < 64; ++i) {
        int r = r0 + half + 2 * i;
        s += g_colw[r] * g_hn[(size_t)r * DD + d];
    }
    red[tid] = s;
    __syncthreads();
    if (tid < 128) atomicAdd(&g_m[tid], red[tid] + red[tid + 128]);
}

// ---------------- mm[d] = Wmb2[d] + sum_k m[k] * Wm2[d][k] ----------------
// 128 blocks (one per d), 128 threads (one per k); g_m is 512B, cache-hot.
__global__ void __launch_bounds__(128) mm_kernel(const float* __restrict__ Wm2,
                                                 const float* __restrict__ Wmb2) {
    __shared__ float red[128];
    const int d = blockIdx.x;
    const int k = threadIdx.x;
    red[k] = g_m[k] * Wm2[d * DD + k];
    __syncthreads();
    if (k < 64) red[k] += red[k + 64];
    __syncthreads();
    if (k < 32) {
        float v = red[k] + red[k + 32];
        #pragma unroll
        for (int o = 16; o > 0; o >>= 1) v += __shfl_down_sync(0xffffffffu, v, o);
        if (k == 0) g_mm[d] = Wmb2[d] + v;
    }
}

// ---------------- out = relu(h_n + mm): pure stream, 1 float4 / thread ----------------
__global__ void __launch_bounds__(256) epi_kernel(float* __restrict__ out) {
    const int gid = blockIdx.x * 256 + threadIdx.x;   // 2048*256 = 524288 float4s
    const int c4 = gid & 31;
    float4 mv = reinterpret_cast<const float4*>(g_mm)[c4];
    float4 h  = reinterpret_cast<const float4*>(g_hn)[gid];
    float4 o;
    o.x = fmaxf(h.x + mv.x, 0.f);
    o.y = fmaxf(h.y + mv.y, 0.f);
    o.z = fmaxf(h.z + mv.z, 0.f);
    o.w = fmaxf(h.w + mv.w, 0.f);
    reinterpret_cast<float4*>(out)[gid] = o;
}

// ---------------- launch: single stream, overlap is structural ----------------
extern "C" void kernel_launch(void* const* d_in, const int* in_sizes, int n_in,
                              void* d_out, int out_size) {
    const int*   x    = (const int*)d_in[0];
    const int*   ea   = (const int*)d_in[1];
    const float* bond = (const float*)d_in[2];
    const float* aemb = (const float*)d_in[3];
    const float* bemb = (const float*)d_in[4];
    const float* Wi_w = (const float*)d_in[5];
    const float* Wi_b = (const float*)d_in[6];
    const float* Wm_w = (const float*)d_in[7];
    const float* Wm_b = (const float*)d_in[8];
    float* out = (float*)d_out;

    // only layer L-1 = 2 contributes to the output (h is not fed back)
    const float* Wi2  = Wi_w + 2 * DD * K2;
    const float* Wib2 = Wi_b + 2 * DD;
    const float* Wm2  = Wm_w + 2 * DD * DD;
    const float* Wmb2 = Wm_b + 2 * DD;

    prep_kernel<<<128, 256>>>(Wi2);
    fused_kernel<<<GEMM_BLOCKS + COLW_BLOCKS, 256>>>(bond, x, ea, aemb, bemb, Wib2);
    m_kernel<<<128, 256>>>();
    mm_kernel<<<128, 128>>>(Wm2, Wmb2);
    epi_kernel<<<2048, 256>>>(out);
}